// round 2
// baseline (speedup 1.0000x reference)
#include <cuda_runtime.h>
#include <math.h>

#define TT 512
#define BB 256
#define DD 256
#define HH 256
#define KK 256
#define GG 1024  // 4*H

// Scratch state (static device globals: allocation-free per harness rules)
__device__ float g_gx[(size_t)TT * BB * GG];   // precomputed x-path gates + biases
__device__ float g_h[2][BB * HH];              // double-buffered hidden state
__device__ float g_c[BB * HH];                 // cell state

// ---------------------------------------------------------------------------
// init: h = h0, c = c0
// ---------------------------------------------------------------------------
__global__ void init_state(const float* __restrict__ h0, const float* __restrict__ c0) {
    int i = blockIdx.x * blockDim.x + threadIdx.x;
    if (i < BB * HH) {
        g_h[0][i] = h0[i];
        g_c[i] = c0[i];
    }
}

// ---------------------------------------------------------------------------
// gemm_x: g_gx[m, n] = sum_k X[m,k]*MX[m&255,k]*W[n,k] + bih[n] + bhh[n]
//   M = TT*BB = 131072, N = GG = 1024, K = 256
//   Tiles: 128x128x8, 256 threads, 8x8 microtile.
// ---------------------------------------------------------------------------
__global__ __launch_bounds__(256) void gemm_x_kernel(
    const float* __restrict__ X, const float* __restrict__ MX,
    const float* __restrict__ W, const float* __restrict__ bih,
    const float* __restrict__ bhh)
{
    __shared__ float As[8][132];
    __shared__ float Bs[8][132];
    const int m0 = blockIdx.x * 128;
    const int n0 = blockIdx.y * 128;
    const int tid = threadIdx.x;

    // loader: 1024 elems per tile, 4 (one float4) per thread
    const int lr = tid >> 1;            // row within tile 0..127
    const int lk = (tid & 1) * 4;       // k offset 0 or 4

    const int tx = tid & 15;            // col group (8 cols each)
    const int ty = tid >> 4;            // row group (8 rows each)

    float acc[8][8];
#pragma unroll
    for (int i = 0; i < 8; i++)
#pragma unroll
        for (int j = 0; j < 8; j++) acc[i][j] = 0.0f;

    const int mrow = m0 + lr;
    const int mxrow = mrow & (BB - 1);

    for (int k0 = 0; k0 < KK; k0 += 8) {
        float4 xa = *(const float4*)(X + (size_t)mrow * KK + k0 + lk);
        float4 ma = *(const float4*)(MX + (size_t)mxrow * KK + k0 + lk);
        As[lk + 0][lr] = xa.x * ma.x;
        As[lk + 1][lr] = xa.y * ma.y;
        As[lk + 2][lr] = xa.z * ma.z;
        As[lk + 3][lr] = xa.w * ma.w;
        float4 wb = *(const float4*)(W + (size_t)(n0 + lr) * KK + k0 + lk);
        Bs[lk + 0][lr] = wb.x;
        Bs[lk + 1][lr] = wb.y;
        Bs[lk + 2][lr] = wb.z;
        Bs[lk + 3][lr] = wb.w;
        __syncthreads();

#pragma unroll
        for (int k = 0; k < 8; k++) {
            float4 a0 = *(const float4*)&As[k][ty * 8];
            float4 a1 = *(const float4*)&As[k][ty * 8 + 4];
            float4 b0 = *(const float4*)&Bs[k][tx * 8];
            float4 b1 = *(const float4*)&Bs[k][tx * 8 + 4];
            float av[8] = {a0.x, a0.y, a0.z, a0.w, a1.x, a1.y, a1.z, a1.w};
            float bv[8] = {b0.x, b0.y, b0.z, b0.w, b1.x, b1.y, b1.z, b1.w};
#pragma unroll
            for (int i = 0; i < 8; i++)
#pragma unroll
                for (int j = 0; j < 8; j++) acc[i][j] += av[i] * bv[j];
        }
        __syncthreads();
    }

    float bsum[8];
#pragma unroll
    for (int j = 0; j < 8; j++) {
        int n = n0 + tx * 8 + j;
        bsum[j] = bih[n] + bhh[n];
    }
#pragma unroll
    for (int i = 0; i < 8; i++) {
        size_t base = (size_t)(m0 + ty * 8 + i) * GG + n0 + tx * 8;
        float4 s0 = make_float4(acc[i][0] + bsum[0], acc[i][1] + bsum[1],
                                acc[i][2] + bsum[2], acc[i][3] + bsum[3]);
        float4 s1 = make_float4(acc[i][4] + bsum[4], acc[i][5] + bsum[5],
                                acc[i][6] + bsum[6], acc[i][7] + bsum[7]);
        *(float4*)&g_gx[base] = s0;
        *(float4*)&g_gx[base + 4] = s1;
    }
}

// ---------------------------------------------------------------------------
// step: gates = gx[t] + (h⊙mask_h) @ W_hh^T ; LSTM pointwise; write out/h/c.
//   Block: 64 batch rows x 8 h-cols (x 4 gates) = 2048 gate outputs.
//   Grid: (256/64) x (256/8) = 4 x 32 = 128 blocks. 128 threads, 4x4 microtile.
//   Thread (tx,ty): h-col j = j0+tx, rows b0+ty*4..+3, all four gates in regs,
//   so the LSTM pointwise is fully local to the thread.
// ---------------------------------------------------------------------------
__device__ __forceinline__ float sigf(float x) { return 1.0f / (1.0f + expf(-x)); }

__global__ __launch_bounds__(128) void step_kernel(
    const float* __restrict__ MH, const float* __restrict__ Whh,
    const int* __restrict__ bsz, float* __restrict__ out, int t)
{
    __shared__ float As[16][68];   // (h*mask_h) tile, transposed [k][row]
    __shared__ float Ws[16][36];   // W_hh tile: col c = gate*8 + jlocal

    const int b0 = blockIdx.x * 64;
    const int j0 = blockIdx.y * 8;
    const int tid = threadIdx.x;
    const int par = t & 1;

    // A loader: 64 rows x 16 k = 1024 floats, 8 per thread (2x float4)
    const int ar = tid >> 1;
    const int ak = (tid & 1) * 8;
    // W loader: 32 gate-cols x 16 k = 512 floats, 4 per thread (1x float4)
    const int wc = tid >> 2;             // 0..31
    const int wk = (tid & 3) * 4;
    const int wrow = ((wc >> 3) << 8) + j0 + (wc & 7);   // gate*256 + j

    const int tx = tid & 7;              // h-col within tile
    const int ty = tid >> 3;             // row group (4 rows each), 0..15

    const float* __restrict__ hprev = g_h[par];
    float* __restrict__ hnext = g_h[par ^ 1];

    float acc[4][4];   // [gate][row]
#pragma unroll
    for (int r = 0; r < 4; r++) {
        int b = b0 + ty * 4 + r;
        size_t base = ((size_t)t * BB + b) * GG + j0 + tx;
        acc[0][r] = g_gx[base];
        acc[1][r] = g_gx[base + 256];
        acc[2][r] = g_gx[base + 512];
        acc[3][r] = g_gx[base + 768];
    }

    const size_t arow = (size_t)(b0 + ar) * HH;
    for (int k0 = 0; k0 < KK; k0 += 16) {
        float4 h0v = *(const float4*)&hprev[arow + k0 + ak];
        float4 h1v = *(const float4*)&hprev[arow + k0 + ak + 4];
        float4 m0v = *(const float4*)&MH[arow + k0 + ak];
        float4 m1v = *(const float4*)&MH[arow + k0 + ak + 4];
        As[ak + 0][ar] = h0v.x * m0v.x;
        As[ak + 1][ar] = h0v.y * m0v.y;
        As[ak + 2][ar] = h0v.z * m0v.z;
        As[ak + 3][ar] = h0v.w * m0v.w;
        As[ak + 4][ar] = h1v.x * m1v.x;
        As[ak + 5][ar] = h1v.y * m1v.y;
        As[ak + 6][ar] = h1v.z * m1v.z;
        As[ak + 7][ar] = h1v.w * m1v.w;
        float4 wv = *(const float4*)&Whh[(size_t)wrow * KK + k0 + wk];
        Ws[wk + 0][wc] = wv.x;
        Ws[wk + 1][wc] = wv.y;
        Ws[wk + 2][wc] = wv.z;
        Ws[wk + 3][wc] = wv.w;
        __syncthreads();

#pragma unroll
        for (int k = 0; k < 16; k++) {
            float4 a = *(const float4*)&As[k][ty * 4];
            float w0 = Ws[k][tx];
            float w1 = Ws[k][8 + tx];
            float w2 = Ws[k][16 + tx];
            float w3 = Ws[k][24 + tx];
            acc[0][0] += w0 * a.x; acc[0][1] += w0 * a.y; acc[0][2] += w0 * a.z; acc[0][3] += w0 * a.w;
            acc[1][0] += w1 * a.x; acc[1][1] += w1 * a.y; acc[1][2] += w1 * a.z; acc[1][3] += w1 * a.w;
            acc[2][0] += w2 * a.x; acc[2][1] += w2 * a.y; acc[2][2] += w2 * a.z; acc[2][3] += w2 * a.w;
            acc[3][0] += w3 * a.x; acc[3][1] += w3 * a.y; acc[3][2] += w3 * a.z; acc[3][3] += w3 * a.w;
        }
        __syncthreads();
    }

    const int size = bsz[t];
    const int j = j0 + tx;
#pragma unroll
    for (int r = 0; r < 4; r++) {
        int b = b0 + ty * 4 + r;
        float iv = sigf(acc[0][r]);
        float fv = sigf(acc[1][r]);
        float gv = tanhf(acc[2][r]);
        float ov = sigf(acc[3][r]);
        float cprev = g_c[b * HH + j];
        float cn = fv * cprev + iv * gv;
        float hn = ov * tanhf(cn);
        bool active = b < size;
        float hpv = hprev[b * HH + j];
        hnext[b * HH + j] = active ? hn : hpv;     // carry state forward
        if (active) g_c[b * HH + j] = cn;
        out[((size_t)t * BB + b) * HH + j] = active ? hn : 0.0f;
    }
}

// ---------------------------------------------------------------------------
// final: hn = g_h[0] (T=512 even -> last write parity 0), cn = g_c
// ---------------------------------------------------------------------------
__global__ void final_kernel(float* __restrict__ out) {
    int i = blockIdx.x * blockDim.x + threadIdx.x;
    if (i < BB * HH) {
        const size_t TBH = (size_t)TT * BB * HH;
        out[TBH + i] = g_h[0][i];
        out[TBH + BB * HH + i] = g_c[i];
    }
}

// ---------------------------------------------------------------------------
extern "C" void kernel_launch(void* const* d_in, const int* in_sizes, int n_in,
                              void* d_out, int out_size)
{
    const float* X   = (const float*)d_in[0];   // [T,B,D]
    const float* h0  = (const float*)d_in[1];   // [B,H]
    const float* c0  = (const float*)d_in[2];   // [B,H]
    const float* mx  = (const float*)d_in[3];   // [B,D]
    const float* mh  = (const float*)d_in[4];   // [B,H]
    const float* Wih = (const float*)d_in[5];   // [4H,D]
    const float* Whh = (const float*)d_in[6];   // [4H,H]
    const float* bih = (const float*)d_in[7];   // [4H]
    const float* bhh = (const float*)d_in[8];   // [4H]
    const int*   bsz = (const int*)d_in[9];     // [T]
    float* out = (float*)d_out;                 // [T*B*H] ++ [B*H] ++ [B*H]

    init_state<<<(BB * HH + 255) / 256, 256>>>(h0, c0);
    gemm_x_kernel<<<dim3((TT * BB) / 128, GG / 128), 256>>>(X, mx, Wih, bih, bhh);
    for (int t = 0; t < TT; t++) {
        step_kernel<<<dim3(BB / 64, HH / 8), 128>>>(mh, Whh, bsz, out, t);
    }
    final_kernel<<<(BB * HH + 255) / 256, 256>>>(out);
}

// round 4
// speedup vs baseline: 1.5489x; 1.5489x over previous
#include <cuda_runtime.h>
#include <math.h>

#define TT 512
#define BB 256
#define DD 256
#define HH 256
#define KK 256
#define GG 1024  // 4*H

#define NBLK 256     // persistent grid: 8 batch-blocks x 32 col-blocks
#define NTHR 128

// Scratch state (static device globals: allocation-free per harness rules)
__device__ float g_gx[(size_t)TT * BB * GG];   // precomputed x-path gates + biases
__device__ float g_hm[2][BB * HH];             // double-buffered (h .* mask_h)
__device__ unsigned g_bar = 0;                 // grid barrier counter
__device__ unsigned g_gen = 0;                 // grid barrier generation

// ---------------------------------------------------------------------------
// gemm_x: g_gx[m, n] = sum_k X[m,k]*MX[m&255,k]*W[n,k] + bih[n] + bhh[n]
//   M = TT*BB = 131072, N = GG = 1024, K = 256. 128x128x8 tiles, 8x8 microtile.
// ---------------------------------------------------------------------------
__global__ __launch_bounds__(256) void gemm_x_kernel(
    const float* __restrict__ X, const float* __restrict__ MX,
    const float* __restrict__ W, const float* __restrict__ bih,
    const float* __restrict__ bhh)
{
    __shared__ float As[8][132];
    __shared__ float Bs[8][132];
    const int m0 = blockIdx.x * 128;
    const int n0 = blockIdx.y * 128;
    const int tid = threadIdx.x;

    const int lr = tid >> 1;
    const int lk = (tid & 1) * 4;
    const int tx = tid & 15;
    const int ty = tid >> 4;

    float acc[8][8];
#pragma unroll
    for (int i = 0; i < 8; i++)
#pragma unroll
        for (int j = 0; j < 8; j++) acc[i][j] = 0.0f;

    const int mrow = m0 + lr;
    const int mxrow = mrow & (BB - 1);

    for (int k0 = 0; k0 < KK; k0 += 8) {
        float4 xa = *(const float4*)(X + (size_t)mrow * KK + k0 + lk);
        float4 ma = *(const float4*)(MX + (size_t)mxrow * KK + k0 + lk);
        As[lk + 0][lr] = xa.x * ma.x;
        As[lk + 1][lr] = xa.y * ma.y;
        As[lk + 2][lr] = xa.z * ma.z;
        As[lk + 3][lr] = xa.w * ma.w;
        float4 wb = *(const float4*)(W + (size_t)(n0 + lr) * KK + k0 + lk);
        Bs[lk + 0][lr] = wb.x;
        Bs[lk + 1][lr] = wb.y;
        Bs[lk + 2][lr] = wb.z;
        Bs[lk + 3][lr] = wb.w;
        __syncthreads();

#pragma unroll
        for (int k = 0; k < 8; k++) {
            float4 a0 = *(const float4*)&As[k][ty * 8];
            float4 a1 = *(const float4*)&As[k][ty * 8 + 4];
            float4 b0 = *(const float4*)&Bs[k][tx * 8];
            float4 b1 = *(const float4*)&Bs[k][tx * 8 + 4];
            float av[8] = {a0.x, a0.y, a0.z, a0.w, a1.x, a1.y, a1.z, a1.w};
            float bv[8] = {b0.x, b0.y, b0.z, b0.w, b1.x, b1.y, b1.z, b1.w};
#pragma unroll
            for (int i = 0; i < 8; i++)
#pragma unroll
                for (int j = 0; j < 8; j++) acc[i][j] += av[i] * bv[j];
        }
        __syncthreads();
    }

    float bsum[8];
#pragma unroll
    for (int j = 0; j < 8; j++) {
        int n = n0 + tx * 8 + j;
        bsum[j] = bih[n] + bhh[n];
    }
#pragma unroll
    for (int i = 0; i < 8; i++) {
        size_t base = (size_t)(m0 + ty * 8 + i) * GG + n0 + tx * 8;
        float4 s0 = make_float4(acc[i][0] + bsum[0], acc[i][1] + bsum[1],
                                acc[i][2] + bsum[2], acc[i][3] + bsum[3]);
        float4 s1 = make_float4(acc[i][4] + bsum[4], acc[i][5] + bsum[5],
                                acc[i][6] + bsum[6], acc[i][7] + bsum[7]);
        *(float4*)&g_gx[base] = s0;
        *(float4*)&g_gx[base + 4] = s1;
    }
}

// ---------------------------------------------------------------------------
// Grid-wide barrier. Co-residency of all NBLK blocks is guaranteed by
// __launch_bounds__(NTHR, 2): 2 CTAs/SM * 148 SMs = 296 >= 256.
// ---------------------------------------------------------------------------
__device__ __forceinline__ void grid_barrier()
{
    __threadfence();          // drain global stores to L2
    __syncthreads();
    if (threadIdx.x == 0) {
        unsigned gen = *(volatile unsigned*)&g_gen;   // read BEFORE arriving
        if (atomicAdd(&g_bar, 1u) == (unsigned)(NBLK - 1)) {
            g_bar = 0;
            __threadfence();
            *(volatile unsigned*)&g_gen = gen + 1;    // release
        } else {
            while (*(volatile unsigned*)&g_gen == gen) { __nanosleep(20); }
        }
    }
    __syncthreads();
}

// ---------------------------------------------------------------------------
// Persistent recurrent kernel.
//   Grid 256 = 8 batch-blocks (32 rows) x 32 col-blocks (8 h-cols x 4 gates).
//   128 threads: tx = h-col (8), ty = row-pair (16). Thread owns 2 (b,j) cells
//   for the whole run: c, h, mask_h live in registers. W_hh slice (32KB) lives
//   in smem for the whole run. Per step: hm tile streamed from L2 (ld.cg,
//   double-buffered 32-k chunks), 8 FFMA/k/thread, pointwise, 1 grid barrier.
// ---------------------------------------------------------------------------
__device__ __forceinline__ float sigf(float x) { return 1.0f / (1.0f + expf(-x)); }

__global__ __launch_bounds__(NTHR, 2) void recurrent_kernel(
    const float* __restrict__ mh, const float* __restrict__ Whh,
    const int* __restrict__ bsz, const float* __restrict__ h0,
    const float* __restrict__ c0, float* __restrict__ out)
{
    __shared__ float Ws[KK][8][4];        // [k][jlocal][gate] = 32 KB
    __shared__ float As[2][32][33];       // double-buffered hm k-chunk

    const int bb = blockIdx.x >> 5;       // 0..7
    const int cb = blockIdx.x & 31;       // 0..31
    const int b0 = bb * 32;
    const int j0 = cb * 8;
    const int tid = threadIdx.x;
    const int tx = tid & 7;               // h-col
    const int ty = tid >> 3;              // row-pair index 0..15
    const int r0 = b0 + ty * 2;           // first of 2 owned rows
    const int j = j0 + tx;

    // ---- one-time: W_hh slice -> smem as [k][jl][gate] ----
    for (int rr = tid >> 5; rr < 32; rr += 4) {       // warp per (g,jl) row
        int g = rr >> 3, jl = rr & 7;
        const float* src = Whh + (size_t)(g * 256 + j0 + jl) * KK;
        for (int k = (tid & 31); k < KK; k += 32)
            Ws[k][jl][g] = src[k];
    }

    // ---- one-time: register state ----
    float mhv[2], cc[2], hh[2];
#pragma unroll
    for (int r = 0; r < 2; r++) {
        int b = r0 + r;
        mhv[r] = mh[b * HH + j];
        cc[r] = c0[b * HH + j];
        hh[r] = h0[b * HH + j];
        g_hm[0][b * HH + j] = hh[r] * mhv[r];
    }
    __syncthreads();
    grid_barrier();     // hm[0] visible everywhere; Ws ready

    // chunk loader mapping: 32 rows x 32 k per chunk, 8 floats/thread
    const int lr = tid >> 2;              // 0..31 row
    const int lk = (tid & 3) * 8;         // k offset within chunk

    for (int t = 0; t < TT; t++) {
        const float* __restrict__ hmp = g_hm[t & 1];
        float* __restrict__ hmn = g_hm[(t & 1) ^ 1];

        // acc init from precomputed x-path gates
        float a00, a01, a02, a03, a10, a11, a12, a13;
        {
            size_t gbase = ((size_t)t * BB + r0) * GG + j;
            a00 = g_gx[gbase];        a01 = g_gx[gbase + 256];
            a02 = g_gx[gbase + 512];  a03 = g_gx[gbase + 768];
            a10 = g_gx[gbase + GG];       a11 = g_gx[gbase + GG + 256];
            a12 = g_gx[gbase + GG + 512]; a13 = g_gx[gbase + GG + 768];
        }

        const float* hrow = hmp + (size_t)(b0 + lr) * HH + lk;

        // preload chunk 0
        float4 v0 = __ldcg((const float4*)(hrow + 0));
        float4 v1 = __ldcg((const float4*)(hrow + 4));
#pragma unroll
        for (int i = 0; i < 4; i++) {
            As[0][lk + i][lr] = ((const float*)&v0)[i];
            As[0][lk + 4 + i][lr] = ((const float*)&v1)[i];
        }
        __syncthreads();

#pragma unroll
        for (int c = 0; c < 8; c++) {
            if (c < 7) {
                v0 = __ldcg((const float4*)(hrow + (c + 1) * 32));
                v1 = __ldcg((const float4*)(hrow + (c + 1) * 32 + 4));
            }
            const int buf = c & 1;
            const int kb = c * 32;
#pragma unroll
            for (int k = 0; k < 32; k++) {
                float ax = As[buf][k][ty * 2];
                float ay = As[buf][k][ty * 2 + 1];
                const float4 w = *(const float4*)&Ws[kb + k][tx][0];
                a00 += ax * w.x; a01 += ax * w.y; a02 += ax * w.z; a03 += ax * w.w;
                a10 += ay * w.x; a11 += ay * w.y; a12 += ay * w.z; a13 += ay * w.w;
            }
            __syncthreads();
            if (c < 7) {
                const int nbuf = (c + 1) & 1;
#pragma unroll
                for (int i = 0; i < 4; i++) {
                    As[nbuf][lk + i][lr] = ((const float*)&v0)[i];
                    As[nbuf][lk + 4 + i][lr] = ((const float*)&v1)[i];
                }
                __syncthreads();
            }
        }

        // pointwise LSTM (2 owned rows)
        const int size = __ldg(bsz + t);
        {
            float iv = sigf(a00), fv = sigf(a01), gv = tanhf(a02), ov = sigf(a03);
            float cn = fv * cc[0] + iv * gv;
            float hn = ov * tanhf(cn);
            bool act = r0 < size;
            if (act) { cc[0] = cn; hh[0] = hn; }
            out[((size_t)t * BB + r0) * HH + j] = act ? hn : 0.0f;
            hmn[r0 * HH + j] = hh[0] * mhv[0];
        }
        {
            float iv = sigf(a10), fv = sigf(a11), gv = tanhf(a12), ov = sigf(a13);
            float cn = fv * cc[1] + iv * gv;
            float hn = ov * tanhf(cn);
            bool act = (r0 + 1) < size;
            if (act) { cc[1] = cn; hh[1] = hn; }
            out[((size_t)t * BB + r0 + 1) * HH + j] = act ? hn : 0.0f;
            hmn[(r0 + 1) * HH + j] = hh[1] * mhv[1];
        }

        grid_barrier();
    }

    // final hn, cn
    const size_t TBH = (size_t)TT * BB * HH;
#pragma unroll
    for (int r = 0; r < 2; r++) {
        int b = r0 + r;
        out[TBH + b * HH + j] = hh[r];
        out[TBH + BB * HH + b * HH + j] = cc[r];
    }
}

// ---------------------------------------------------------------------------
extern "C" void kernel_launch(void* const* d_in, const int* in_sizes, int n_in,
                              void* d_out, int out_size)
{
    const float* X   = (const float*)d_in[0];   // [T,B,D]
    const float* h0  = (const float*)d_in[1];   // [B,H]
    const float* c0  = (const float*)d_in[2];   // [B,H]
    const float* mx  = (const float*)d_in[3];   // [B,D]
    const float* mh  = (const float*)d_in[4];   // [B,H]
    const float* Wih = (const float*)d_in[5];   // [4H,D]
    const float* Whh = (const float*)d_in[6];   // [4H,H]
    const float* bih = (const float*)d_in[7];   // [4H]
    const float* bhh = (const float*)d_in[8];   // [4H]
    const int*   bsz = (const int*)d_in[9];     // [T]
    float* out = (float*)d_out;                 // [T*B*H] ++ [B*H] ++ [B*H]

    gemm_x_kernel<<<dim3((TT * BB) / 128, GG / 128), 256>>>(X, mx, Wih, bih, bhh);
    recurrent_kernel<<<NBLK, NTHR>>>(mh, Whh, bsz, h0, c0, out);
}

// round 5
// speedup vs baseline: 1.7333x; 1.1190x over previous
#include <cuda_runtime.h>
#include <math.h>

#define TT 512
#define BB 256
#define DD 256
#define HH 256
#define KK 256
#define GG 1024  // 4*H

#define NBLK 256     // persistent grid: 8 batch-blocks x 32 col-blocks
#define NTHR 128

// Scratch state (static device globals: allocation-free per harness rules)
__device__ float g_gx[(size_t)TT * BB * GG];   // precomputed x-path gates + biases
__device__ float g_hm[2][BB * HH];             // double-buffered (h .* mask_h)
__device__ unsigned g_bar = 0;                 // grid barrier counter
__device__ unsigned g_gen = 0;                 // grid barrier generation

// ---------------------------------------------------------------------------
// gemm_x: g_gx[m, n] = sum_k X[m,k]*MX[m&255,k]*W[n,k] + bih[n] + bhh[n]
// ---------------------------------------------------------------------------
__global__ __launch_bounds__(256) void gemm_x_kernel(
    const float* __restrict__ X, const float* __restrict__ MX,
    const float* __restrict__ W, const float* __restrict__ bih,
    const float* __restrict__ bhh)
{
    __shared__ float As[8][132];
    __shared__ float Bs[8][132];
    const int m0 = blockIdx.x * 128;
    const int n0 = blockIdx.y * 128;
    const int tid = threadIdx.x;

    const int lr = tid >> 1;
    const int lk = (tid & 1) * 4;
    const int tx = tid & 15;
    const int ty = tid >> 4;

    float acc[8][8];
#pragma unroll
    for (int i = 0; i < 8; i++)
#pragma unroll
        for (int j = 0; j < 8; j++) acc[i][j] = 0.0f;

    const int mrow = m0 + lr;
    const int mxrow = mrow & (BB - 1);

    for (int k0 = 0; k0 < KK; k0 += 8) {
        float4 xa = *(const float4*)(X + (size_t)mrow * KK + k0 + lk);
        float4 ma = *(const float4*)(MX + (size_t)mxrow * KK + k0 + lk);
        As[lk + 0][lr] = xa.x * ma.x;
        As[lk + 1][lr] = xa.y * ma.y;
        As[lk + 2][lr] = xa.z * ma.z;
        As[lk + 3][lr] = xa.w * ma.w;
        float4 wb = *(const float4*)(W + (size_t)(n0 + lr) * KK + k0 + lk);
        Bs[lk + 0][lr] = wb.x;
        Bs[lk + 1][lr] = wb.y;
        Bs[lk + 2][lr] = wb.z;
        Bs[lk + 3][lr] = wb.w;
        __syncthreads();

#pragma unroll
        for (int k = 0; k < 8; k++) {
            float4 a0 = *(const float4*)&As[k][ty * 8];
            float4 a1 = *(const float4*)&As[k][ty * 8 + 4];
            float4 b0 = *(const float4*)&Bs[k][tx * 8];
            float4 b1 = *(const float4*)&Bs[k][tx * 8 + 4];
            float av[8] = {a0.x, a0.y, a0.z, a0.w, a1.x, a1.y, a1.z, a1.w};
            float bv[8] = {b0.x, b0.y, b0.z, b0.w, b1.x, b1.y, b1.z, b1.w};
#pragma unroll
            for (int i = 0; i < 8; i++)
#pragma unroll
                for (int j = 0; j < 8; j++) acc[i][j] += av[i] * bv[j];
        }
        __syncthreads();
    }

    float bsum[8];
#pragma unroll
    for (int j = 0; j < 8; j++) {
        int n = n0 + tx * 8 + j;
        bsum[j] = bih[n] + bhh[n];
    }
#pragma unroll
    for (int i = 0; i < 8; i++) {
        size_t base = (size_t)(m0 + ty * 8 + i) * GG + n0 + tx * 8;
        float4 s0 = make_float4(acc[i][0] + bsum[0], acc[i][1] + bsum[1],
                                acc[i][2] + bsum[2], acc[i][3] + bsum[3]);
        float4 s1 = make_float4(acc[i][4] + bsum[4], acc[i][5] + bsum[5],
                                acc[i][6] + bsum[6], acc[i][7] + bsum[7]);
        *(float4*)&g_gx[base] = s0;
        *(float4*)&g_gx[base + 4] = s1;
    }
}

// ---------------------------------------------------------------------------
// Grid-wide barrier. Co-residency guaranteed by __launch_bounds__(NTHR, 2).
// ---------------------------------------------------------------------------
__device__ __forceinline__ void grid_barrier()
{
    __threadfence();          // drain hm stores to L2
    __syncthreads();
    if (threadIdx.x == 0) {
        unsigned gen = *(volatile unsigned*)&g_gen;   // read BEFORE arriving
        if (atomicAdd(&g_bar, 1u) == (unsigned)(NBLK - 1)) {
            g_bar = 0;
            __threadfence();
            *(volatile unsigned*)&g_gen = gen + 1;    // release
        } else {
            while (*(volatile unsigned*)&g_gen == gen) { }
        }
    }
    __syncthreads();
}

// Fast, overflow-safe transcendentals (~2-ulp __expf; plenty for 1e-3 budget)
__device__ __forceinline__ float fsig(float x) {
    return __fdividef(1.0f, 1.0f + __expf(-x));
}
__device__ __forceinline__ float ftanh(float x) {
    // 2*sigmoid(2x)-1: large +x -> exp->0 -> 1; large -x -> exp->inf -> -1
    return __fdividef(2.0f, 1.0f + __expf(-2.0f * x)) - 1.0f;
}

// ---------------------------------------------------------------------------
// Persistent recurrent kernel.
//   Grid 256 = 8 batch-blocks (32 rows) x 32 col-blocks (8 h-cols x 4 gates).
//   Per step: hm tile streamed from L2 in 8 reg-prefetched 32-k chunks with
//   ONE sync per chunk; 8 FFMA/k/thread; fast pointwise; out stores deferred
//   past the grid barrier so the fence only drains the hm stores.
// ---------------------------------------------------------------------------
__global__ __launch_bounds__(NTHR, 2) void recurrent_kernel(
    const float* __restrict__ mh, const float* __restrict__ Whh,
    const int* __restrict__ bsz, const float* __restrict__ h0,
    const float* __restrict__ c0, float* __restrict__ out)
{
    __shared__ float Ws[KK][8][4];        // [k][jlocal][gate] = 32 KB
    __shared__ float As[2][32][34];       // hm chunk, padded for aligned LDS.64
    __shared__ int   Sbsz[TT];            // 2 KB

    const int bb = blockIdx.x >> 5;       // 0..7
    const int cb = blockIdx.x & 31;       // 0..31
    const int b0 = bb * 32;
    const int j0 = cb * 8;
    const int tid = threadIdx.x;
    const int tx = tid & 7;               // h-col
    const int ty = tid >> 3;              // row-pair index 0..15
    const int r0 = b0 + ty * 2;           // first of 2 owned rows
    const int j = j0 + tx;

    // ---- one-time: W_hh slice -> smem as [k][jl][gate] ----
    for (int rr = tid >> 5; rr < 32; rr += 4) {       // warp per (g,jl) row
        int g = rr >> 3, jl = rr & 7;
        const float* src = Whh + (size_t)(g * 256 + j0 + jl) * KK;
        for (int k = (tid & 31); k < KK; k += 32)
            Ws[k][jl][g] = src[k];
    }
    for (int i = tid; i < TT; i += NTHR) Sbsz[i] = bsz[i];

    // ---- one-time: register state ----
    float mhv[2], cc[2], hh[2];
#pragma unroll
    for (int r = 0; r < 2; r++) {
        int b = r0 + r;
        mhv[r] = mh[b * HH + j];
        cc[r] = c0[b * HH + j];
        hh[r] = h0[b * HH + j];
        g_hm[0][b * HH + j] = hh[r] * mhv[r];
    }
    __syncthreads();
    grid_barrier();     // hm[0] visible everywhere; Ws/Sbsz ready

    // chunk loader mapping: 32 rows x 32 k per chunk, 8 floats/thread
    const int lr = tid >> 2;              // 0..31 row
    const int lk = (tid & 3) * 8;         // k offset within chunk
    const size_t hoff = (size_t)(b0 + lr) * HH + lk;

    for (int t = 0; t < TT; t++) {
        const float* __restrict__ hmp = g_hm[t & 1];
        float* __restrict__ hmn = g_hm[(t & 1) ^ 1];
        const float* hrow = hmp + hoff;

        // acc init from precomputed x-path gates (ld.cg; consumed ~600cyc later)
        float a00, a01, a02, a03, a10, a11, a12, a13;
        {
            const float* gp = g_gx + ((size_t)t * BB + r0) * GG + j;
            a00 = __ldcg(gp);        a01 = __ldcg(gp + 256);
            a02 = __ldcg(gp + 512);  a03 = __ldcg(gp + 768);
            a10 = __ldcg(gp + GG);       a11 = __ldcg(gp + GG + 256);
            a12 = __ldcg(gp + GG + 512); a13 = __ldcg(gp + GG + 768);
        }

        // preload chunk 0
        float4 p0 = __ldcg((const float4*)(hrow + 0));
        float4 p1 = __ldcg((const float4*)(hrow + 4));
#pragma unroll
        for (int i = 0; i < 4; i++) {
            As[0][lk + i][lr] = ((const float*)&p0)[i];
            As[0][lk + 4 + i][lr] = ((const float*)&p1)[i];
        }
        __syncthreads();

#pragma unroll
        for (int c = 0; c < 8; c++) {
            const int buf = c & 1;
            if (c < 7) {   // prefetch next chunk (hidden under compute)
                p0 = __ldcg((const float4*)(hrow + (c + 1) * 32));
                p1 = __ldcg((const float4*)(hrow + (c + 1) * 32 + 4));
            }
            const int kb = c * 32;
#pragma unroll
            for (int k = 0; k < 32; k++) {
                float2 a = *(const float2*)&As[buf][k][ty * 2];
                const float4 w = *(const float4*)&Ws[kb + k][tx][0];
                a00 = fmaf(a.x, w.x, a00); a01 = fmaf(a.x, w.y, a01);
                a02 = fmaf(a.x, w.z, a02); a03 = fmaf(a.x, w.w, a03);
                a10 = fmaf(a.y, w.x, a10); a11 = fmaf(a.y, w.y, a11);
                a12 = fmaf(a.y, w.z, a12); a13 = fmaf(a.y, w.w, a13);
            }
            if (c < 7) {   // store prefetch into the buffer nobody is reading
#pragma unroll
                for (int i = 0; i < 4; i++) {
                    As[buf ^ 1][lk + i][lr] = ((const float*)&p0)[i];
                    As[buf ^ 1][lk + 4 + i][lr] = ((const float*)&p1)[i];
                }
                __syncthreads();   // one sync per chunk
            }
        }

        // pointwise LSTM (2 owned rows); hm stores on critical path, out deferred
        const int size = Sbsz[t];
        float o0, o1;
        {
            float iv = fsig(a00), fv = fsig(a01), gv = ftanh(a02), ov = fsig(a03);
            float cn = fv * cc[0] + iv * gv;
            float hn = ov * ftanh(cn);
            bool act = r0 < size;
            if (act) { cc[0] = cn; hh[0] = hn; }
            o0 = act ? hn : 0.0f;
            hmn[r0 * HH + j] = hh[0] * mhv[0];
        }
        {
            float iv = fsig(a10), fv = fsig(a11), gv = ftanh(a12), ov = fsig(a13);
            float cn = fv * cc[1] + iv * gv;
            float hn = ov * ftanh(cn);
            bool act = (r0 + 1) < size;
            if (act) { cc[1] = cn; hh[1] = hn; }
            o1 = act ? hn : 0.0f;
            hmn[(r0 + 1) * HH + j] = hh[1] * mhv[1];
        }

        grid_barrier();

        // out stores after the barrier: fence above doesn't wait on them
        out[((size_t)t * BB + r0) * HH + j] = o0;
        out[((size_t)t * BB + r0 + 1) * HH + j] = o1;
    }

    // final hn, cn
    const size_t TBH = (size_t)TT * BB * HH;
#pragma unroll
    for (int r = 0; r < 2; r++) {
        int b = r0 + r;
        out[TBH + b * HH + j] = hh[r];
        out[TBH + BB * HH + b * HH + j] = cc[r];
    }
}

// ---------------------------------------------------------------------------
extern "C" void kernel_launch(void* const* d_in, const int* in_sizes, int n_in,
                              void* d_out, int out_size)
{
    const float* X   = (const float*)d_in[0];   // [T,B,D]
    const float* h0  = (const float*)d_in[1];   // [B,H]
    const float* c0  = (const float*)d_in[2];   // [B,H]
    const float* mx  = (const float*)d_in[3];   // [B,D]
    const float* mh  = (const float*)d_in[4];   // [B,H]
    const float* Wih = (const float*)d_in[5];   // [4H,D]
    const float* Whh = (const float*)d_in[6];   // [4H,H]
    const float* bih = (const float*)d_in[7];   // [4H]
    const float* bhh = (const float*)d_in[8];   // [4H]
    const int*   bsz = (const int*)d_in[9];     // [T]
    float* out = (float*)d_out;                 // [T*B*H] ++ [B*H] ++ [B*H]

    gemm_x_kernel<<<dim3((TT * BB) / 128, GG / 128), 256>>>(X, mx, Wih, bih, bhh);
    recurrent_kernel<<<NBLK, NTHR>>>(mh, Whh, bsz, h0, c0, out);
}